// round 17
// baseline (speedup 1.0000x reference)
#include <cuda_runtime.h>

#define NN 50000
#define NE 800000
#define FD 64
#define GROUP 128          // nodes per block-group (8 per warp) in k_final
#define NPW 8              // nodes per warp in k_final
#define ABLOCKS 444        // build kernel: 3 blocks/SM x 148 SMs, all co-resident
#define ATHREADS 512

// ---------------- scratch (static device globals; no runtime alloc) ----------------
// g_deg/g_cnt/g_total zero at load and re-zeroed by k_final's tail each run.
// g_bcount self-resets per barrier; g_bgen is monotonic (relative compares only).
__device__ float g_deg[NN];
__device__ float g_dinv[NN];
__device__ int   g_cnt[NN];
__device__ __align__(16) int2 g_span[NN];  // (off, end) per node
__device__ int   g_cur[NN];
__device__ int   g_total;
__device__ unsigned g_bcount;
__device__ unsigned g_bgen;
__device__ __align__(16) int2  g_edge[NE];          // (src, weight-bits) bucketed by dst
__device__ __align__(16) float g_tx1[NN * FD];
__device__ __align__(16) float g_s2[NN * FD];
__device__ __align__(16) float g_wc[7 * FD * FD];   // combined weights, [mat][k][f]
__device__ float g_bias[3 * FD];                    // bz, bh, blin

typedef unsigned long long ull;

// ---------------- f32x2 packed helpers (sm_103a dual-fp32 datapath) ----------------
__device__ __forceinline__ ull dup2(float a) {
    ull r;
    asm("mov.b64 %0, {%1, %1};" : "=l"(r) : "f"(a));
    return r;
}
__device__ __forceinline__ void fma2(ull& d, ull a, ull b) {
    asm("fma.rn.f32x2 %0, %1, %2, %0;" : "+l"(d) : "l"(a), "l"(b));
}
__device__ __forceinline__ void unpk2(ull v, float& x, float& y) {
    asm("mov.b64 {%0, %1}, %2;" : "=f"(x), "=f"(y) : "l"(v));
}

// ---------------- software grid barrier (all ABLOCKS co-resident by construction) --
__device__ __forceinline__ void grid_bar() {
    __syncthreads();
    if (threadIdx.x == 0) {
        __threadfence();                                  // release own block's writes
        unsigned gen = *((volatile unsigned*)&g_bgen);    // exact: release of this
                                                          // barrier can't precede our arrival
        if (atomicAdd(&g_bcount, 1u) == ABLOCKS - 1u) {
            atomicExch(&g_bcount, 0u);
            __threadfence();
            atomicAdd(&g_bgen, 1u);                       // release all
        } else {
            while (*((volatile unsigned*)&g_bgen) == gen) {}
        }
        __threadfence();                                  // acquire
    }
    __syncthreads();
}

// ---------------- gather core: ONE WARP per dst node, 4 edges/warp-iter ------------
__device__ __forceinline__ float4 gather_node(const float4* __restrict__ in4,
                                              int node, int half, int qlane) {
    int2 span = g_span[node];
    int beg = span.x, end = span.y;
    float4 a0 = make_float4(0.f, 0.f, 0.f, 0.f);
    float4 a1 = a0;
    int i = beg;
    for (; i + 3 < end; i += 4) {
        int2 e0 = __ldcs(&g_edge[i + half]);
        int2 e1 = __ldcs(&g_edge[i + 2 + half]);
        float4 v0 = in4[e0.x * 16 + qlane];
        float4 v1 = in4[e1.x * 16 + qlane];
        float w0 = __int_as_float(e0.y), w1 = __int_as_float(e1.y);
        a0.x = fmaf(w0, v0.x, a0.x); a0.y = fmaf(w0, v0.y, a0.y);
        a0.z = fmaf(w0, v0.z, a0.z); a0.w = fmaf(w0, v0.w, a0.w);
        a1.x = fmaf(w1, v1.x, a1.x); a1.y = fmaf(w1, v1.y, a1.y);
        a1.z = fmaf(w1, v1.z, a1.z); a1.w = fmaf(w1, v1.w, a1.w);
    }
    if (i + half < end) {
        int2 e0 = __ldcs(&g_edge[i + half]);
        float4 v0 = in4[e0.x * 16 + qlane];
        float w0 = __int_as_float(e0.y);
        a0.x = fmaf(w0, v0.x, a0.x); a0.y = fmaf(w0, v0.y, a0.y);
        a0.z = fmaf(w0, v0.z, a0.z); a0.w = fmaf(w0, v0.w, a0.w);
    }
    if (i + 2 + half < end) {
        int2 e1 = __ldcs(&g_edge[i + 2 + half]);
        float4 v1 = in4[e1.x * 16 + qlane];
        float w1 = __int_as_float(e1.y);
        a1.x = fmaf(w1, v1.x, a1.x); a1.y = fmaf(w1, v1.y, a1.y);
        a1.z = fmaf(w1, v1.z, a1.z); a1.w = fmaf(w1, v1.w, a1.w);
    }
    a0.x += a1.x; a0.y += a1.y; a0.z += a1.z; a0.w += a1.w;
    a0.x += __shfl_xor_sync(0xFFFFFFFFu, a0.x, 16);
    a0.y += __shfl_xor_sync(0xFFFFFFFFu, a0.y, 16);
    a0.z += __shfl_xor_sync(0xFFFFFFFFu, a0.z, 16);
    a0.w += __shfl_xor_sync(0xFFFFFFFFu, a0.w, 16);
    return a0;
}

// ---------------- persistent build kernel: hist|prep|permute|gather1|gather2 -------
__global__ void __launch_bounds__(ATHREADS, 3)
k_build(const int* __restrict__ src, const int* __restrict__ dst,
        const float* __restrict__ ew, const float* __restrict__ x,
        const float* __restrict__ Wxz, const float* __restrict__ bxz,
        const float* __restrict__ bhz,
        const float* __restrict__ Wxh, const float* __restrict__ bxh,
        const float* __restrict__ bhh,
        const float* __restrict__ Wlin, const float* __restrict__ blin) {
    const int gtid = blockIdx.x * ATHREADS + threadIdx.x;
    const int lane = threadIdx.x & 31;

    // ---- phase 1: histogram (4 edges/thread, fire-and-forget REDs) ----
    if (gtid * 4 < NE) {
        int4   s4 = reinterpret_cast<const int4*>(src)[gtid];
        int4   d4 = reinterpret_cast<const int4*>(dst)[gtid];
        float4 w4 = reinterpret_cast<const float4*>(ew)[gtid];
        atomicAdd(&g_deg[s4.x], w4.x); atomicAdd(&g_cnt[d4.x], 1);
        atomicAdd(&g_deg[s4.y], w4.y); atomicAdd(&g_cnt[d4.y], 1);
        atomicAdd(&g_deg[s4.z], w4.z); atomicAdd(&g_cnt[d4.z], 1);
        atomicAdd(&g_deg[s4.w], w4.w); atomicAdd(&g_cnt[d4.w], 1);
    }
    grid_bar();

    // ---- phase 2: dinv + bucket allocation (bump allocator) + weight/bias prep ----
    {
        int i = gtid;
        int c = (i < NN) ? g_cnt[i] : 0;
        int scan = c;
        #pragma unroll
        for (int d = 1; d < 32; d <<= 1) {
            int v = __shfl_up_sync(0xFFFFFFFFu, scan, d);
            if (lane >= d) scan += v;
        }
        int warpsum = __shfl_sync(0xFFFFFFFFu, scan, 31);
        int base = 0;
        if (lane == 31 && warpsum > 0) base = atomicAdd(&g_total, warpsum);
        base = __shfl_sync(0xFFFFFFFFu, base, 31);
        if (i < NN) {
            int off = base + scan - c;
            g_span[i] = make_int2(off, off + c);
            g_cur[i] = off;
            float dg = g_deg[i];
            g_dinv[i] = (dg > 0.f) ? rsqrtf(dg) : 0.f;
        }
        if (i < FD * FD) {
            // Tx2 = 2*S2 - Tx0  =>  W0' = W0 - W2, W2' = 2*W2
            g_wc[0 * 4096 + i] = Wxz[i] - Wxz[2 * 4096 + i];
            g_wc[1 * 4096 + i] = Wxz[4096 + i];
            g_wc[2 * 4096 + i] = 2.f * Wxz[2 * 4096 + i];
            g_wc[3 * 4096 + i] = Wxh[i] - Wxh[2 * 4096 + i];
            g_wc[4 * 4096 + i] = Wxh[4096 + i];
            g_wc[5 * 4096 + i] = 2.f * Wxh[2 * 4096 + i];
            g_wc[6 * 4096 + i] = Wlin[i];
        }
        if (i < FD) {
            g_bias[i]          = bxz[i] + bhz[i];   // H0=0 => cheb(H0)=b_hz
            g_bias[FD + i]     = bxh[i] + bhh[i];
            g_bias[2 * FD + i] = blin[i];
        }
    }
    grid_bar();

    // ---- phase 3: permute (4 edges/thread, streaming stores) ----
    if (gtid * 4 < NE) {
        int4   s4 = reinterpret_cast<const int4*>(src)[gtid];
        int4   d4 = reinterpret_cast<const int4*>(dst)[gtid];
        float4 w4 = reinterpret_cast<const float4*>(ew)[gtid];
        float c0 = -w4.x * g_dinv[s4.x] * g_dinv[d4.x];
        float c1 = -w4.y * g_dinv[s4.y] * g_dinv[d4.y];
        float c2 = -w4.z * g_dinv[s4.z] * g_dinv[d4.z];
        float c3 = -w4.w * g_dinv[s4.w] * g_dinv[d4.w];
        int p0 = atomicAdd(&g_cur[d4.x], 1);
        int p1 = atomicAdd(&g_cur[d4.y], 1);
        int p2 = atomicAdd(&g_cur[d4.z], 1);
        int p3 = atomicAdd(&g_cur[d4.w], 1);
        __stcs(&g_edge[p0], make_int2(s4.x, __float_as_int(c0)));
        __stcs(&g_edge[p1], make_int2(s4.y, __float_as_int(c1)));
        __stcs(&g_edge[p2], make_int2(s4.z, __float_as_int(c2)));
        __stcs(&g_edge[p3], make_int2(s4.w, __float_as_int(c3)));
    }
    grid_bar();

    // ---- phase 4: gather hop 1 (x -> tx1), warp per node, grid-stride ----
    {
        const int nwarps = ABLOCKS * (ATHREADS / 32);
        const int w0 = gtid >> 5;
        const int half = lane >> 4, qlane = lane & 15;
        const float4* in4 = reinterpret_cast<const float4*>(x);
        for (int node = w0; node < NN; node += nwarps) {
            float4 a = gather_node(in4, node, half, qlane);
            if (half == 0)
                reinterpret_cast<float4*>(g_tx1)[node * 16 + qlane] = a;
        }
    }
    grid_bar();

    // ---- phase 5: gather hop 2 (tx1 -> s2) ----
    {
        const int nwarps = ABLOCKS * (ATHREADS / 32);
        const int w0 = gtid >> 5;
        const int half = lane >> 4, qlane = lane & 15;
        const float4* in4 = reinterpret_cast<const float4*>(g_tx1);
        for (int node = w0; node < NN; node += nwarps) {
            float4 a = gather_node(in4, node, half, qlane);
            if (half == 0)
                reinterpret_cast<float4*>(g_s2)[node * 16 + qlane] = a;
        }
    }
}

// ---------------- fused dense kernel: 128 nodes/group, 8 nodes/warp --------------
#define SMEM_FLOATS (7 * 4096 + 192 + GROUP * 192)

__global__ void __launch_bounds__(512, 1)
k_final(const float* __restrict__ x, float* __restrict__ out) {
    extern __shared__ float sm[];
    float* sW  = sm;                   // 7*4096
    float* sB  = sW + 7 * 4096;       // 192
    float* sTx = sB + 192;            // GROUP nodes * (Tx0|Tx1|S2) * 64
    float* sH  = sTx;                 // overlay: GROUP*64 after mainloop

    const int tid = threadIdx.x;
    for (int i = tid; i < 7 * 4096; i += 512) sW[i] = g_wc[i];
    for (int i = tid; i < 192; i += 512) sB[i] = g_bias[i];

    const int warp = tid >> 5, lane = tid & 31;
    const int f = lane * 2;
    const int ngroups = (NN + GROUP - 1) / GROUP;

    for (int g = blockIdx.x; g < ngroups; g += gridDim.x) {
        const int base = g * GROUP;
        for (int i = tid; i < GROUP * 16; i += 512) {
            int node = i >> 4, q = i & 15;
            int n = base + node;
            float4 a, b, c;
            if (n < NN) {
                a = reinterpret_cast<const float4*>(x)[n * 16 + q];
                b = reinterpret_cast<const float4*>(g_tx1)[n * 16 + q];
                c = reinterpret_cast<const float4*>(g_s2)[n * 16 + q];
            } else {
                a = make_float4(0.f, 0.f, 0.f, 0.f); b = a; c = a;
            }
            reinterpret_cast<float4*>(sTx)[node * 48 + q]      = a;
            reinterpret_cast<float4*>(sTx)[node * 48 + 16 + q] = b;
            reinterpret_cast<float4*>(sTx)[node * 48 + 32 + q] = c;
        }
        __syncthreads();

        ull az[NPW], ah[NPW];
        {
            ull bz = *(const ull*)&sB[f];
            ull bh = *(const ull*)&sB[64 + f];
            #pragma unroll
            for (int j = 0; j < NPW; j++) { az[j] = bz; ah[j] = bh; }
        }
        const float* t = sTx + (warp * NPW) * 192;

        for (int k4 = 0; k4 < 64; k4 += 4) {
            #pragma unroll
            for (int m = 0; m < 3; m++) {
                ull wz[4], wh[4];
                #pragma unroll
                for (int kk = 0; kk < 4; kk++) {
                    wz[kk] = *(const ull*)&sW[m * 4096 + (k4 + kk) * 64 + f];
                    wh[kk] = *(const ull*)&sW[(m + 3) * 4096 + (k4 + kk) * 64 + f];
                }
                float4 Am[NPW];
                #pragma unroll
                for (int j = 0; j < NPW; j++)
                    Am[j] = *(const float4*)&t[j * 192 + m * 64 + k4];
                #pragma unroll
                for (int kk = 0; kk < 4; kk++) {
                    #pragma unroll
                    for (int j = 0; j < NPW; j++) {
                        const float* pa = (const float*)&Am[j];
                        ull a = dup2(pa[kk]);
                        fma2(az[j], a, wz[kk]);
                        fma2(ah[j], a, wh[kk]);
                    }
                }
            }
        }

        float Hx[NPW], Hy[NPW];
        #pragma unroll
        for (int j = 0; j < NPW; j++) {
            float azx, azy, ahx, ahy;
            unpk2(az[j], azx, azy);
            unpk2(ah[j], ahx, ahy);
            float zx = 1.f / (1.f + __expf(-azx));
            float zy = 1.f / (1.f + __expf(-azy));
            float hx = 1.f - 2.f / (__expf(2.f * ahx) + 1.f);
            float hy = 1.f - 2.f / (__expf(2.f * ahy) + 1.f);
            Hx[j] = fmaxf((1.f - zx) * hx, 0.f);
            Hy[j] = fmaxf((1.f - zy) * hy, 0.f);
        }
        __syncthreads();   // all warps done reading sTx before H overlay

        #pragma unroll
        for (int j = 0; j < NPW; j++) {
            int node = warp * NPW + j;
            sH[node * 64 + f]     = Hx[j];
            sH[node * 64 + f + 1] = Hy[j];
        }

        ull o[NPW];
        {
            ull bl = *(const ull*)&sB[128 + f];
            #pragma unroll
            for (int j = 0; j < NPW; j++) o[j] = bl;
        }
        for (int k4 = 0; k4 < 64; k4 += 4) {
            ull wl[4];
            #pragma unroll
            for (int kk = 0; kk < 4; kk++)
                wl[kk] = *(const ull*)&sW[6 * 4096 + (k4 + kk) * 64 + f];
            float4 Hv[NPW];
            #pragma unroll
            for (int j = 0; j < NPW; j++)
                Hv[j] = *(const float4*)&sH[(warp * NPW + j) * 64 + k4];
            #pragma unroll
            for (int kk = 0; kk < 4; kk++) {
                #pragma unroll
                for (int j = 0; j < NPW; j++) {
                    const float* ph = (const float*)&Hv[j];
                    fma2(o[j], dup2(ph[kk]), wl[kk]);
                }
            }
        }
        #pragma unroll
        for (int j = 0; j < NPW; j++) {
            int n = base + warp * NPW + j;
            if (n < NN) {
                float ox, oy;
                unpk2(o[j], ox, oy);
                *(float2*)&out[n * 64 + f] = make_float2(ox, oy);
            }
        }
        __syncthreads();
    }

    // tail: restore zeroed state for the next invocation
    for (int i = blockIdx.x * 512 + tid; i < NN; i += gridDim.x * 512) {
        g_deg[i] = 0.f;
        g_cnt[i] = 0;
    }
    if (blockIdx.x == 0 && tid == 0) g_total = 0;
}

// ---------------- launch ----------------
extern "C" void kernel_launch(void* const* d_in, const int* in_sizes, int n_in,
                              void* d_out, int out_size) {
    const float* x    = (const float*)d_in[0];
    const int*   ei   = (const int*)d_in[1];
    const float* ew   = (const float*)d_in[2];
    const float* Wxz  = (const float*)d_in[3];
    const float* bxz  = (const float*)d_in[4];
    const float* bhz  = (const float*)d_in[6];   // W_hz unused (H0 = 0)
    const float* Wxh  = (const float*)d_in[11];
    const float* bxh  = (const float*)d_in[12];
    const float* bhh  = (const float*)d_in[14];  // W_hh unused
    const float* Wlin = (const float*)d_in[15];
    const float* blin = (const float*)d_in[16];
    float* out = (float*)d_out;

    const int* src = ei;
    const int* dst = ei + NE;

    cudaFuncSetAttribute(k_final, cudaFuncAttributeMaxDynamicSharedMemorySize,
                         SMEM_FLOATS * (int)sizeof(float));

    k_build<<<ABLOCKS, ATHREADS>>>(src, dst, ew, x,
                                   Wxz, bxz, bhz, Wxh, bxh, bhh, Wlin, blin);
    k_final<<<148, 512, SMEM_FLOATS * (int)sizeof(float)>>>(x, out);
}